// round 16
// baseline (speedup 1.0000x reference)
#include <cuda_runtime.h>
#include <cuda_fp16.h>
#include <mma.h>
#include <cstdint>

using namespace nvcuda;

#define BATCH 65536
#define KDIM  784
#define KPAD  800           // 25 * 32, zero-padded weights
#define NDIM  256
#define OUTD  10

#define BM 128
#define BN 256
#define BK 32
#define NITER (KPAD / BK)   // 25
#define XLD 40              // x smem ld (elems), 80B rows
#define WLD 264             // w smem ld (elems), 528B rows
#define THREADS 512         // 16 warps: 4 (M) x 4 (N), warp tile 32x64
#define DEC_LD 20           // decode ld (80B)

// ---- smem layout (bytes) ----
#define XH_OFF(b) ((b) * 10240)             // 128*40*2
#define WH_OFF(b) (20480 + (b) * 16896)     // 32*264*2
#define SOUT_OFF  54272                     // 128*12 floats
#define B1_OFF    60416                     // 256 floats
#define W2_OFF    61440                     // 256*12 floats
#define B2_OFF    73728                     // 12 floats
#define SMEM_BYTES 73776

// Persistent weights (allocation-free rule: device globals), single fp16
__device__ __half g_Wh[KPAD * NDIM];

__device__ __forceinline__ uint32_t smem_u32(const void* p) {
    uint32_t a;
    asm("{ .reg .u64 t; cvta.to.shared.u64 t, %1; cvt.u32.u64 %0, t; }" : "=r"(a) : "l"(p));
    return a;
}
__device__ __forceinline__ void cp_async16(uint32_t dst, const void* src) {
    asm volatile("cp.async.ca.shared.global [%0], [%1], 16;" :: "r"(dst), "l"(src) : "memory");
}
#define CP_COMMIT() asm volatile("cp.async.commit_group;" ::: "memory")
#define CP_WAIT0()  asm volatile("cp.async.wait_group 0;" ::: "memory")

// ---------------------------------------------------------------------------
// prep: fold conv into W1_eff = C^T * w1, single fp16 (rows >= 784 zero)
// ---------------------------------------------------------------------------
__global__ void prep_kernel(const float* __restrict__ w_conv,
                            const float* __restrict__ w1) {
    int q = blockIdx.x;        // 0..799
    int n = threadIdx.x;       // 0..255
    float s = 0.f;
    if (q < KDIM) {
        int r = q / 28, c = q % 28;
#pragma unroll
        for (int i = 0; i < 3; i++) {
            int pr = r - i;
            if (pr < 0 || pr >= 26) continue;
#pragma unroll
            for (int j = 0; j < 3; j++) {
                int pc = c - j;
                if (pc < 0 || pc >= 26) continue;
                s += w_conv[i * 3 + j] * w1[(pr * 26 + pc) * NDIM + n];
            }
        }
    }
    g_Wh[q * NDIM + n] = __float2half_rn(s);
}

// ---------------------------------------------------------------------------
// Fused: out = relu(x @ W1_eff + b1) @ w2 + b2
// Single-term fp16 MMA, fp32 accumulate. CTA 128x256, 16 warps of 32x64.
// BK=32, ping-pong smem; x via LDG+convert, W via cp.async.
// ---------------------------------------------------------------------------
extern "C" __global__ void __launch_bounds__(THREADS, 1)
fused_kernel(const float* __restrict__ x,
             const float* __restrict__ b1,
             const float* __restrict__ w2,
             const float* __restrict__ b2,
             float* __restrict__ out) {
    extern __shared__ __align__(128) char sm[];
    uint32_t smb = smem_u32(sm);

    int tid   = threadIdx.x;
    int warp  = tid >> 5;
    int lane  = tid & 31;
    int warpM = warp >> 2;               // 0..3 (32-row strips)
    int warpN = warp & 3;                // 0..3 (64-col strips)
    int rowBase = blockIdx.x * BM;

    float* s_out = reinterpret_cast<float*>(sm + SOUT_OFF);
    float* s_b1  = reinterpret_cast<float*>(sm + B1_OFF);
    float* s_w2  = reinterpret_cast<float*>(sm + W2_OFF);
    float* s_b2  = reinterpret_cast<float*>(sm + B2_OFF);

    // ---- epilogue constants + accumulator init ----
    for (int i = tid; i < NDIM; i += THREADS) s_b1[i] = b1[i];
    for (int i = tid; i < NDIM; i += THREADS) {
#pragma unroll
        for (int j = 0; j < OUTD; j++) s_w2[i * 12 + j] = w2[i * OUTD + j];
        s_w2[i * 12 + 10] = 0.f; s_w2[i * 12 + 11] = 0.f;
    }
    if (tid < 12) s_b2[tid] = (tid < OUTD) ? b2[tid] : 0.f;
    for (int i = tid; i < BM * 12; i += THREADS) s_out[i] = 0.f;

    wmma::fragment<wmma::accumulator, 16, 16, 16, float> acc[2][4];
#pragma unroll
    for (int mi = 0; mi < 2; mi++)
#pragma unroll
        for (int ni = 0; ni < 4; ni++)
            wmma::fill_fragment(acc[mi][ni], 0.0f);

    // loader mapping
    int xr = tid >> 2;               // 0..127
    int xc = (tid & 3) * 8;          // 0,8,16,24 (8 fp32 per thread)
    int wr = tid >> 4;               // 0..31
    int wc = (tid & 15) * 16;        // 0..240 (16 halfs = 32B per thread)

    const float* xptr = x + (size_t)(rowBase + xr) * KDIM + xc;
    const __half* whp = g_Wh + (size_t)wr * NDIM + wc;
    uint32_t wdst = smb + (uint32_t)(wr * WLD + wc) * 2;   // + WH_OFF(buf)

    auto stage_x = [&](int buf, int k0) {
        __half hb[8];
        if (k0 + xc + 8 <= KDIM) {   // chunks are fully valid or fully OOB (784-768=16, mult of 8)
            float4 v0 = *reinterpret_cast<const float4*>(xptr + k0);
            float4 v1 = *reinterpret_cast<const float4*>(xptr + k0 + 4);
            hb[0] = __float2half_rn(v0.x); hb[1] = __float2half_rn(v0.y);
            hb[2] = __float2half_rn(v0.z); hb[3] = __float2half_rn(v0.w);
            hb[4] = __float2half_rn(v1.x); hb[5] = __float2half_rn(v1.y);
            hb[6] = __float2half_rn(v1.z); hb[7] = __float2half_rn(v1.w);
        } else {
#pragma unroll
            for (int i = 0; i < 8; i++) hb[i] = __float2half_rn(0.f);
        }
        *reinterpret_cast<uint4*>(sm + XH_OFF(buf) + (xr * XLD + xc) * 2) =
            *reinterpret_cast<uint4*>(hb);
    };
    auto issue_w = [&](int blk, int buf) {
        size_t off = (size_t)blk * BK * NDIM;
        cp_async16(wdst + WH_OFF(buf),      whp + off);
        cp_async16(wdst + WH_OFF(buf) + 16, whp + off + 8);
        CP_COMMIT();
    };

    // ---- prologue: stage block 0 into buf 0 ----
    issue_w(0, 0);
    stage_x(0, 0);
    CP_WAIT0();
    __syncthreads();

    for (int it = 0; it < NITER; it++) {
        int cur = it & 1;
        int nxt = cur ^ 1;
        if (it + 1 < NITER) issue_w(it + 1, nxt);

        // ---- compute on current buffer: warp tile 32x64, single term ----
        {
            const __half* xh = reinterpret_cast<const __half*>(sm + XH_OFF(cur));
            const __half* wh = reinterpret_cast<const __half*>(sm + WH_OFF(cur));
#pragma unroll
            for (int ks = 0; ks < 2; ks++) {
                wmma::fragment<wmma::matrix_a, 16, 16, 16, __half, wmma::row_major> ah[2];
#pragma unroll
                for (int mi = 0; mi < 2; mi++)
                    wmma::load_matrix_sync(ah[mi],
                        xh + (warpM * 32 + mi * 16) * XLD + ks * 16, XLD);
#pragma unroll
                for (int ni = 0; ni < 4; ni++) {
                    wmma::fragment<wmma::matrix_b, 16, 16, 16, __half, wmma::row_major> bh;
                    wmma::load_matrix_sync(bh, wh + (ks * 16) * WLD + warpN * 64 + ni * 16, WLD);
#pragma unroll
                    for (int mi = 0; mi < 2; mi++)
                        wmma::mma_sync(acc[mi][ni], ah[mi], bh, acc[mi][ni]);
                }
            }
        }

        if (it + 1 < NITER) {
            stage_x(nxt, (it + 1) * BK);
            CP_WAIT0();
        }
        __syncthreads();
    }

    // ======================= fused epilogue =======================
    // dec strips alias tile region (fully consumed after last sync): 16*1280B = 20480B
    float* dec = reinterpret_cast<float*>(sm) + warp * (16 * DEC_LD);

    int rhalf = lane & 15;
    int chalf = (lane >> 4) * 8;
#pragma unroll
    for (int mi = 0; mi < 2; mi++) {
        int row = warpM * 32 + mi * 16 + rhalf;
        float p[12];
#pragma unroll
        for (int j = 0; j < 12; j++) p[j] = 0.f;
#pragma unroll
        for (int ni = 0; ni < 4; ni++) {
            wmma::store_matrix_sync(dec, acc[mi][ni], DEC_LD, wmma::mem_row_major);
            __syncwarp();
#pragma unroll
            for (int c = 0; c < 8; c++) {
                int n = warpN * 64 + ni * 16 + chalf + c;
                float v = dec[rhalf * DEC_LD + chalf + c] + s_b1[n];
                v = fmaxf(v, 0.f);
                const float4* wrp = reinterpret_cast<const float4*>(s_w2 + n * 12);
                float4 w0 = wrp[0], w1v = wrp[1], w2v = wrp[2];
                p[0]  += v * w0.x;  p[1]  += v * w0.y;  p[2]  += v * w0.z;  p[3]  += v * w0.w;
                p[4]  += v * w1v.x; p[5]  += v * w1v.y; p[6]  += v * w1v.z; p[7]  += v * w1v.w;
                p[8]  += v * w2v.x; p[9]  += v * w2v.y; p[10] += v * w2v.z; p[11] += v * w2v.w;
            }
            __syncwarp();
        }
#pragma unroll
        for (int j = 0; j < OUTD; j++)
            atomicAdd(&s_out[row * 12 + j], p[j]);
    }
    __syncthreads();

    // write out (+ b2)
    for (int i = tid; i < BM * OUTD; i += THREADS) {
        int r = i / OUTD, j = i - r * OUTD;
        out[(size_t)(rowBase + r) * OUTD + j] = s_out[r * 12 + j] + s_b2[j];
    }
}

// ---------------------------------------------------------------------------
extern "C" void kernel_launch(void* const* d_in, const int* in_sizes, int n_in,
                              void* d_out, int out_size) {
    const float* x      = (const float*)d_in[0];
    const float* w_conv = (const float*)d_in[1];
    const float* w1     = (const float*)d_in[2];
    const float* b1     = (const float*)d_in[3];
    const float* w2     = (const float*)d_in[4];
    const float* b2     = (const float*)d_in[5];
    float* out = (float*)d_out;

    cudaFuncSetAttribute(fused_kernel,
                         cudaFuncAttributeMaxDynamicSharedMemorySize, SMEM_BYTES);

    prep_kernel<<<KPAD, NDIM>>>(w_conv, w1);
    fused_kernel<<<BATCH / BM, THREADS, SMEM_BYTES>>>(x, b1, w2, b2, out);
}

// round 17
// speedup vs baseline: 1.6248x; 1.6248x over previous
#include <cuda_runtime.h>
#include <cuda_fp16.h>
#include <mma.h>
#include <cstdint>

using namespace nvcuda;

#define BATCH 65536
#define KDIM  784
#define KPAD  800           // 25 * 32, zero-padded weights
#define NDIM  256
#define OUTD  10

#define BM 128
#define BN 256
#define BK 32
#define NITER (KPAD / BK)   // 25
#define XLD 40              // x smem ld (elems), 80B rows
#define WLD 264             // w smem ld (elems), 528B rows
#define THREADS 256         // 8 warps: 2 (M) x 4 (N), warp tile 64x64
#define DEC_LD 20           // decode ld (80B)

// ---- smem layout (bytes) ----
#define XH_OFF(b) ((b) * 10240)             // 128*40*2
#define WH_OFF(b) (20480 + (b) * 16896)     // 32*264*2
#define SOUT_OFF  54272                     // 128*12 floats
#define B1_OFF    60416                     // 256 floats
#define W2_OFF    61440                     // 256*12 floats
#define B2_OFF    73728                     // 12 floats
#define SMEM_BYTES 73776

// Persistent weights (allocation-free rule: device globals), single fp16
__device__ __half g_Wh[KPAD * NDIM];

__device__ __forceinline__ uint32_t smem_u32(const void* p) {
    uint32_t a;
    asm("{ .reg .u64 t; cvta.to.shared.u64 t, %1; cvt.u32.u64 %0, t; }" : "=r"(a) : "l"(p));
    return a;
}
__device__ __forceinline__ void cp_async16(uint32_t dst, const void* src) {
    asm volatile("cp.async.ca.shared.global [%0], [%1], 16;" :: "r"(dst), "l"(src) : "memory");
}
#define CP_COMMIT() asm volatile("cp.async.commit_group;" ::: "memory")
#define CP_WAIT0()  asm volatile("cp.async.wait_group 0;" ::: "memory")

// ---------------------------------------------------------------------------
// prep: fold conv into W1_eff = C^T * w1, single fp16 (rows >= 784 zero)
// ---------------------------------------------------------------------------
__global__ void prep_kernel(const float* __restrict__ w_conv,
                            const float* __restrict__ w1) {
    int q = blockIdx.x;        // 0..799
    int n = threadIdx.x;       // 0..255
    float s = 0.f;
    if (q < KDIM) {
        int r = q / 28, c = q % 28;
#pragma unroll
        for (int i = 0; i < 3; i++) {
            int pr = r - i;
            if (pr < 0 || pr >= 26) continue;
#pragma unroll
            for (int j = 0; j < 3; j++) {
                int pc = c - j;
                if (pc < 0 || pc >= 26) continue;
                s += w_conv[i * 3 + j] * w1[(pr * 26 + pc) * NDIM + n];
            }
        }
    }
    g_Wh[q * NDIM + n] = __float2half_rn(s);
}

// ---------------------------------------------------------------------------
// Fused: out = relu(x @ W1_eff + b1) @ w2 + b2
// Single-term fp16 MMA, fp32 accumulate. CTA 128x256, 8 warps of 64x64.
// BK=32, ping-pong smem; x LDG prefetched at loop-top (hidden under MMAs),
// convert+STS after compute; W via cp.async issued 1 block ahead.
// ---------------------------------------------------------------------------
extern "C" __global__ void __launch_bounds__(THREADS, 1)
fused_kernel(const float* __restrict__ x,
             const float* __restrict__ b1,
             const float* __restrict__ w2,
             const float* __restrict__ b2,
             float* __restrict__ out) {
    extern __shared__ __align__(128) char sm[];
    uint32_t smb = smem_u32(sm);

    int tid   = threadIdx.x;
    int warp  = tid >> 5;
    int lane  = tid & 31;
    int warpM = warp >> 2;               // 0..1 (64-row strips)
    int warpN = warp & 3;                // 0..3 (64-col strips)
    int rowBase = blockIdx.x * BM;

    float* s_out = reinterpret_cast<float*>(sm + SOUT_OFF);
    float* s_b1  = reinterpret_cast<float*>(sm + B1_OFF);
    float* s_w2  = reinterpret_cast<float*>(sm + W2_OFF);
    float* s_b2  = reinterpret_cast<float*>(sm + B2_OFF);

    // ---- epilogue constants + accumulator init ----
    for (int i = tid; i < NDIM; i += THREADS) s_b1[i] = b1[i];
    for (int i = tid; i < NDIM; i += THREADS) {
#pragma unroll
        for (int j = 0; j < OUTD; j++) s_w2[i * 12 + j] = w2[i * OUTD + j];
        s_w2[i * 12 + 10] = 0.f; s_w2[i * 12 + 11] = 0.f;
    }
    if (tid < 12) s_b2[tid] = (tid < OUTD) ? b2[tid] : 0.f;
    for (int i = tid; i < BM * 12; i += THREADS) s_out[i] = 0.f;

    wmma::fragment<wmma::accumulator, 16, 16, 16, float> acc[4][4];
#pragma unroll
    for (int mi = 0; mi < 4; mi++)
#pragma unroll
        for (int ni = 0; ni < 4; ni++)
            wmma::fill_fragment(acc[mi][ni], 0.0f);

    // loader mapping
    int xr = tid >> 1;               // 0..127
    int xc = (tid & 1) * 16;         // 0 or 16 (16 fp32 per thread)
    int wr = tid >> 3;               // 0..31
    int wc = (tid & 7) * 32;         // 0..224 (32 halfs = 64B per thread)

    const float* xptr = x + (size_t)(rowBase + xr) * KDIM + xc;
    const __half* whp = g_Wh + (size_t)wr * NDIM + wc;
    uint32_t wdst = smb + (uint32_t)(wr * WLD + wc) * 2;   // + WH_OFF(buf)

    // x register prefetch (16 floats = 4 float4)
    float4 vx[4];
    auto load_x = [&](int k0) {
        if (k0 + xc < KDIM) {      // chunk fully valid (only k0=768,xc=16 is OOB)
#pragma unroll
            for (int i = 0; i < 4; i++)
                vx[i] = *reinterpret_cast<const float4*>(xptr + k0 + i * 4);
        } else {
#pragma unroll
            for (int i = 0; i < 4; i++) vx[i] = make_float4(0.f, 0.f, 0.f, 0.f);
        }
    };
    auto sts_x = [&](int buf) {
        __half hb[16];
#pragma unroll
        for (int i = 0; i < 4; i++) {
            hb[i * 4 + 0] = __float2half_rn(vx[i].x);
            hb[i * 4 + 1] = __float2half_rn(vx[i].y);
            hb[i * 4 + 2] = __float2half_rn(vx[i].z);
            hb[i * 4 + 3] = __float2half_rn(vx[i].w);
        }
        uint4* dst = reinterpret_cast<uint4*>(sm + XH_OFF(buf) + (xr * XLD + xc) * 2);
        dst[0] = reinterpret_cast<uint4*>(hb)[0];
        dst[1] = reinterpret_cast<uint4*>(hb)[1];
    };
    auto issue_w = [&](int blk, int buf) {
        size_t off = (size_t)blk * BK * NDIM;
#pragma unroll
        for (int i = 0; i < 4; i++)
            cp_async16(wdst + WH_OFF(buf) + i * 16, whp + off + i * 8);
        CP_COMMIT();
    };

    // ---- prologue: stage block 0 into buf 0 ----
    issue_w(0, 0);
    load_x(0);
    sts_x(0);
    CP_WAIT0();
    __syncthreads();

    for (int it = 0; it < NITER; it++) {
        int cur = it & 1;
        int nxt = cur ^ 1;
        // prefetch next: W via cp.async, x into registers (hidden under MMAs)
        if (it + 1 < NITER) {
            issue_w(it + 1, nxt);
            load_x((it + 1) * BK);
        }

        // ---- compute on current buffer: warp tile 64x64, single term ----
        {
            const __half* xh = reinterpret_cast<const __half*>(sm + XH_OFF(cur));
            const __half* wh = reinterpret_cast<const __half*>(sm + WH_OFF(cur));
#pragma unroll
            for (int ks = 0; ks < 2; ks++) {
                wmma::fragment<wmma::matrix_a, 16, 16, 16, __half, wmma::row_major> ah[4];
#pragma unroll
                for (int mi = 0; mi < 4; mi++)
                    wmma::load_matrix_sync(ah[mi],
                        xh + (warpM * 64 + mi * 16) * XLD + ks * 16, XLD);
#pragma unroll
                for (int ni = 0; ni < 4; ni++) {
                    wmma::fragment<wmma::matrix_b, 16, 16, 16, __half, wmma::row_major> bh;
                    wmma::load_matrix_sync(bh, wh + (ks * 16) * WLD + warpN * 64 + ni * 16, WLD);
#pragma unroll
                    for (int mi = 0; mi < 4; mi++)
                        wmma::mma_sync(acc[mi][ni], ah[mi], bh, acc[mi][ni]);
                }
            }
        }

        if (it + 1 < NITER) {
            sts_x(nxt);        // LDG already landed during compute; convert+STS only
            CP_WAIT0();
        }
        __syncthreads();
    }

    // ======================= fused epilogue =======================
    // dec strips alias tile region (fully consumed after last sync): 8*1280B
    float* dec = reinterpret_cast<float*>(sm) + warp * (16 * DEC_LD);

    int rhalf = lane & 15;
    int chalf = (lane >> 4) * 8;
#pragma unroll
    for (int mi = 0; mi < 4; mi++) {
        int row = warpM * 64 + mi * 16 + rhalf;
        float p[12];
#pragma unroll
        for (int j = 0; j < 12; j++) p[j] = 0.f;
#pragma unroll
        for (int ni = 0; ni < 4; ni++) {
            wmma::store_matrix_sync(dec, acc[mi][ni], DEC_LD, wmma::mem_row_major);
            __syncwarp();
#pragma unroll
            for (int c = 0; c < 8; c++) {
                int n = warpN * 64 + ni * 16 + chalf + c;
                float v = dec[rhalf * DEC_LD + chalf + c] + s_b1[n];
                v = fmaxf(v, 0.f);
                const float4* wrp = reinterpret_cast<const float4*>(s_w2 + n * 12);
                float4 w0 = wrp[0], w1v = wrp[1], w2v = wrp[2];
                p[0]  += v * w0.x;  p[1]  += v * w0.y;  p[2]  += v * w0.z;  p[3]  += v * w0.w;
                p[4]  += v * w1v.x; p[5]  += v * w1v.y; p[6]  += v * w1v.z; p[7]  += v * w1v.w;
                p[8]  += v * w2v.x; p[9]  += v * w2v.y; p[10] += v * w2v.z; p[11] += v * w2v.w;
            }
            __syncwarp();
        }
#pragma unroll
        for (int j = 0; j < OUTD; j++)
            atomicAdd(&s_out[row * 12 + j], p[j]);
    }
    __syncthreads();

    // write out (+ b2)
    for (int i = tid; i < BM * OUTD; i += THREADS) {
        int r = i / OUTD, j = i - r * OUTD;
        out[(size_t)(rowBase + r) * OUTD + j] = s_out[r * 12 + j] + s_b2[j];
    }
}

// ---------------------------------------------------------------------------
extern "C" void kernel_launch(void* const* d_in, const int* in_sizes, int n_in,
                              void* d_out, int out_size) {
    const float* x      = (const float*)d_in[0];
    const float* w_conv = (const float*)d_in[1];
    const float* w1     = (const float*)d_in[2];
    const float* b1     = (const float*)d_in[3];
    const float* w2     = (const float*)d_in[4];
    const float* b2     = (const float*)d_in[5];
    float* out = (float*)d_out;

    cudaFuncSetAttribute(fused_kernel,
                         cudaFuncAttributeMaxDynamicSharedMemorySize, SMEM_BYTES);

    prep_kernel<<<KPAD, NDIM>>>(w_conv, w1);
    fused_kernel<<<BATCH / BM, THREADS, SMEM_BYTES>>>(x, b1, w2, b2, out);
}